// round 15
// baseline (speedup 1.0000x reference)
#include <cuda_runtime.h>
#include <cuda_fp16.h>
#include <mma.h>
#include <math.h>

using namespace nvcuda;

// Problem constants
#define BATCH 4
#define AC 32
#define BC 32
#define PS 16
#define KK 9
#define KKA 288
#define H 14
#define OH 7
#define L 49
#define BL 196
#define NPP 3136
#define NPAD 3200
#define NBLK 200         // NPAD/16 column blocks
#define GM 4608          // 16 * 288 fused GEMM M
#define EPSV 1e-12f
#define LN2PI 1.8378770664093453f

// ---------------- device scratch ----------------
__device__ float g_h[16][KKA];
__device__ float g_S[16];
__device__ __half g_Ch[GM][KKA];        // fp16 circulant rows, row = k*16+pf
__device__ float g_PU[KKA][NPAD];       // fp32 unfolded pose
__device__ __half g_PUh[KKA][NPAD];     // fp16 copy for GEMM
__device__ float g_U2[KKA][NBLK][256];  // correction, blocked [k][bl][pf][pp]
__device__ float g_v[BL][KKA][PS][BC];  // votes, TRANSPOSED [bl][k][p][b]
__device__ float g_au[BL][KKA];
__device__ float g_pass0[BL][2][512];   // pass-0 stats

__device__ __forceinline__ void cp16(void* smem_dst, const void* gsrc) {
    unsigned s = (unsigned)__cvta_generic_to_shared(smem_dst);
    asm volatile("cp.async.cg.shared.global [%0], [%1], 16;\n" :: "r"(s), "l"(gsrc));
}
#define CP_COMMIT() asm volatile("cp.async.commit_group;\n")
#define CP_WAIT(n)  asm volatile("cp.async.wait_group %0;\n" :: "n"(n))

// f32 warp max via integer redux (monotonic key mapping; valid for non-NaN).
__device__ __forceinline__ float warp_redux_max_f32(float x) {
    unsigned u = __float_as_uint(x);
    unsigned key = (u & 0x80000000u) ? ~u : (u | 0x80000000u);
    unsigned r;
    asm volatile("redux.sync.max.u32 %0, %1, 0xffffffff;" : "=r"(r) : "r"(key));
    unsigned v = (r & 0x80000000u) ? (r & 0x7fffffffu) : ~r;
    return __uint_as_float(v);
}

// ---------------- kernel 0: circulant kernels h_p, S_p ----------------
__global__ void k_build_h(const float* __restrict__ fw) {
    int p = blockIdx.x;          // 0..15
    int d = threadIdx.x;         // 0..287
    float wr0   = fw[(0 * 16 + p) * 2];
    float wr144 = fw[(144 * 16 + p) * 2];
    float s = 0.f;
    for (int k = 1; k <= 143; ++k) {
        float wr = fw[(k * 16 + p) * 2];
        float wi = fw[(k * 16 + p) * 2 + 1];
        int md = (k * d) % KKA;
        float x = (float)md * (1.0f / 144.0f);
        float sn, cs;
        sincospif(x, &sn, &cs);
        s += wr * cs - wi * sn;
    }
    float h = (wr0 + ((d & 1) ? -wr144 : wr144) + 2.f * s) * (1.0f / (float)KKA);
    g_h[p][d] = h;
    __shared__ float red[KKA];
    red[d] = h;
    __syncthreads();
    if (d == 0) {
        float t = 0.f;
        for (int i = 0; i < KKA; ++i) t += red[i];
        g_S[p] = t;
    }
}

// ---------------- kernel 1: merged setup ----------------
__global__ void k_setup(const float* __restrict__ pose, const float* __restrict__ a_in) {
    __shared__ float tile[16][197];
    __shared__ float ta[196];
    const int tid = threadIdx.x;         // 256

    if (blockIdx.x >= 128) {
        int idx = (blockIdx.x - 128) * 256 + tid;
        if (idx < BL * 2 * 512) ((float*)g_pass0)[idx] = 0.f;
        if (idx < 16 * KKA * KKA) {
            int row = idx / KKA;          // 0..4607 = k*16+pf
            int m = idx - row * KKA;
            int k = row >> 4, pf = row & 15;
            int d = k - m; if (d < 0) d += KKA;
            g_Ch[row][m] = __float2half(g_h[pf][d]);
        }
        return;
    }
    const int blk = blockIdx.x;          // 0..127
    const int batch = blk >> 5;
    const int a = blk & 31;

    const float* src = pose + (size_t)(batch * (AC * PS) + a * PS) * 196;
    for (int i = tid; i < 16 * 196; i += 256) {
        int pp = i / 196, r = i - pp * 196;
        tile[pp][r] = src[pp * 196 + r];
    }
    for (int i = tid; i < 196; i += 256)
        ta[i] = a_in[(batch * AC + a) * 196 + i];
    __syncthreads();

    for (int i = tid; i < 9 * 49 * 16; i += 256) {
        int pp = i & 15;
        int rest = i >> 4;
        int pos = rest % 49;
        int kk = rest / 49;
        int y = pos / 7, x = pos - y * 7;
        int iy = 2 * y - 1 + kk / 3;
        int ix = 2 * x - 1 + (kk - (kk / 3) * 3);
        bool ok = (iy >= 0) & (iy < H) & (ix >= 0) & (ix < H);
        float v = ok ? tile[pp][iy * 14 + ix] : 0.f;
        int m = kk * 32 + a;
        int col = (batch * 49 + pos) * 16 + pp;
        g_PU[m][col] = v;
        g_PUh[m][col] = __float2half(v);
        if (pp == 0)
            g_au[batch * 49 + pos][m] = ok ? ta[iy * 14 + ix] : 0.f;
    }
}

// ---------------- kernel 3: fp16 tensor GEMM, blocked epilogue ----------------
#define LDA 40
#define LDB 72
__global__ void k_gemm() {
    __shared__ __half sA[2][128 * LDA];
    __shared__ __half sB[2][32 * LDB];
    const int tid = threadIdx.x;
    const int row0 = blockIdx.y * 128;
    const int col0 = blockIdx.x * 64;
    const __half* Ag = &g_Ch[0][0];
    const __half* Bg = &g_PUh[0][0];
    const int wm = (tid >> 5) & 3;
    const int wn = tid >> 7;

    wmma::fragment<wmma::accumulator, 16, 16, 16, float> acc[2][2];
#pragma unroll
    for (int i = 0; i < 2; ++i)
#pragma unroll
        for (int j = 0; j < 2; ++j) wmma::fill_fragment(acc[i][j], 0.f);

    {
#pragma unroll
        for (int t = tid; t < 512; t += 256) {
            int r = t >> 2, c = t & 3;
            cp16(&sA[0][r * LDA + c * 8], Ag + (row0 + r) * KKA + c * 8);
        }
        int r = tid >> 3, c = tid & 7;
        cp16(&sB[0][r * LDB + c * 8], Bg + r * NPAD + col0 + c * 8);
        CP_COMMIT();
    }
    int cur = 0;
    for (int kt = 0; kt < 9; ++kt) {
        if (kt < 8) {
            int k0 = (kt + 1) * 32;
            int nxt = cur ^ 1;
#pragma unroll
            for (int t = tid; t < 512; t += 256) {
                int r = t >> 2, c = t & 3;
                cp16(&sA[nxt][r * LDA + c * 8], Ag + (row0 + r) * KKA + k0 + c * 8);
            }
            int r = tid >> 3, c = tid & 7;
            cp16(&sB[nxt][r * LDB + c * 8], Bg + (k0 + r) * NPAD + col0 + c * 8);
            CP_COMMIT();
            CP_WAIT(1);
        } else {
            CP_WAIT(0);
        }
        __syncthreads();
#pragma unroll
        for (int ks = 0; ks < 2; ++ks) {
            wmma::fragment<wmma::matrix_a, 16, 16, 16, __half, wmma::row_major> a0, a1;
            wmma::fragment<wmma::matrix_b, 16, 16, 16, __half, wmma::row_major> b0, b1;
            wmma::load_matrix_sync(a0, &sA[cur][(wm * 32) * LDA + ks * 16], LDA);
            wmma::load_matrix_sync(a1, &sA[cur][(wm * 32 + 16) * LDA + ks * 16], LDA);
            wmma::load_matrix_sync(b0, &sB[cur][(ks * 16) * LDB + wn * 32], LDB);
            wmma::load_matrix_sync(b1, &sB[cur][(ks * 16) * LDB + wn * 32 + 16], LDB);
            wmma::mma_sync(acc[0][0], a0, b0, acc[0][0]);
            wmma::mma_sync(acc[0][1], a0, b1, acc[0][1]);
            wmma::mma_sync(acc[1][0], a1, b0, acc[1][0]);
            wmma::mma_sync(acc[1][1], a1, b1, acc[1][1]);
        }
        __syncthreads();
        cur ^= 1;
    }
    // blocked epilogue: each 16x16 tile = (k fixed, blk16 fixed, pf x pp) -> ld=16
#pragma unroll
    for (int i = 0; i < 2; ++i)
#pragma unroll
        for (int j = 0; j < 2; ++j) {
            int rt = row0 + wm * 32 + i * 16;     // = k*16
            int ct = col0 + wn * 32 + j * 16;     // = blk16*16
            int k = rt >> 4;
            int blb = ct >> 4;
            wmma::store_matrix_sync(&g_U2[k][blb][0], acc[i][j], 16, wmma::mem_row_major);
        }
}

// ---------------- kernel 4: votes + pass-0 stats, transposed v output ------
// thread map: tid = kh*256 + p*16 + bb (bb fastest). outputs b=bb, b=bb+16.
__global__ void __launch_bounds__(512) k_votes(const float* __restrict__ W,
                                               const float* __restrict__ mb) {
    const int bl = blockIdx.x;
    const int k0 = blockIdx.y * 16;
    const int tid = threadIdx.x;      // 512
    __shared__ __align__(16) float Usf[16][16][20];   // [k][pf][pp] pad 20
    __shared__ float sau[16];

    const int kh = tid >> 8;          // 0..1 (k-half)
    const int rr = tid & 255;
    const int p  = rr >> 4;           // 0..15
    const int bb = rr & 15;           // 0..15 (fastest)
    const int o0 = bb * 16 + p;             // (b=bb, p)
    const int o1 = (bb + 16) * 16 + p;      // (b=bb+16, p)

    float w0[16], w1[16];
    {
        const float4* wv0 = (const float4*)(W + o0 * 16);
        const float4* wv1 = (const float4*)(W + o1 * 16);
#pragma unroll
        for (int f = 0; f < 4; ++f) {
            float4 a = wv0[f], c = wv1[f];
            w0[f * 4 + 0] = a.x; w0[f * 4 + 1] = a.y; w0[f * 4 + 2] = a.z; w0[f * 4 + 3] = a.w;
            w1[f * 4 + 0] = c.x; w1[f * 4 + 1] = c.y; w1[f * 4 + 2] = c.z; w1[f * 4 + 3] = c.w;
        }
    }
    if (tid < 16) sau[tid] = g_au[bl][k0 + tid];
    const float gs = 1.f + g_S[p];
    const float sb0 = mb[o0] * gs;
    const float sb1 = mb[o1] * gs;
    const int col = bl * PS;

    // stage 16 k x 16 pf x 16 pp: y = U2 (contiguous 1KB per k) + PU
#pragma unroll
    for (int i = tid; i < 1024; i += 512) {
        int f = i & 3;
        int pf = (i >> 2) & 15;
        int k = i >> 6;               // 0..15
        float4 u4 = *(const float4*)&g_U2[k0 + k][bl][pf * 16 + f * 4];
        float4 r4 = *(const float4*)&g_PU[k0 + k][col + f * 4];
        float4 y;
        y.x = u4.x + r4.x; y.y = u4.y + r4.y;
        y.z = u4.z + r4.z; y.w = u4.w + r4.w;
        *(float4*)&Usf[k][pf][f * 4] = y;
    }
    __syncthreads();
    float aV0 = 0.f, aQ0 = 0.f, aV1 = 0.f, aQ1 = 0.f;
#pragma unroll
    for (int kk = 0; kk < 8; ++kk) {
        int k = kh * 8 + kk;
        const float4* yr = (const float4*)&Usf[k][p][0];
        float4 y0 = yr[0], y1 = yr[1], y2 = yr[2], y3 = yr[3];
        float s0 = sb0, s1 = sb1;
        s0 += y0.x * w0[0]  + y0.y * w0[1]  + y0.z * w0[2]  + y0.w * w0[3];
        s1 += y0.x * w1[0]  + y0.y * w1[1]  + y0.z * w1[2]  + y0.w * w1[3];
        s0 += y1.x * w0[4]  + y1.y * w0[5]  + y1.z * w0[6]  + y1.w * w0[7];
        s1 += y1.x * w1[4]  + y1.y * w1[5]  + y1.z * w1[6]  + y1.w * w1[7];
        s0 += y2.x * w0[8]  + y2.y * w0[9]  + y2.z * w0[10] + y2.w * w0[11];
        s1 += y2.x * w1[8]  + y2.y * w1[9]  + y2.z * w1[10] + y2.w * w1[11];
        s0 += y3.x * w0[12] + y3.y * w0[13] + y3.z * w0[14] + y3.w * w0[15];
        s1 += y3.x * w1[12] + y3.y * w1[13] + y3.z * w1[14] + y3.w * w1[15];
        g_v[bl][k0 + k][p][bb] = s0;          // transposed store, coalesced (bb fastest)
        g_v[bl][k0 + k][p][bb + 16] = s1;
        float auk = sau[k];
        aV0 += auk * s0; aQ0 += auk * s0 * s0;
        aV1 += auk * s1; aQ1 += auk * s1 * s1;
    }
    atomicAdd(&g_pass0[bl][0][o0], aV0);
    atomicAdd(&g_pass0[bl][1][o0], aQ0);
    atomicAdd(&g_pass0[bl][0][o1], aV1);
    atomicAdd(&g_pass0[bl][1][o1], aQ1);
}

// ---------------- kernel 5: fused EM routing, coalesced transposed v loads ----
__global__ void __launch_bounds__(512) k_em(const float* __restrict__ beta_u,
                                            const float* __restrict__ beta_a,
                                            float* __restrict__ out) {
    const int bl = blockIdx.x;        // 196
    const int tid = threadIdx.x;      // 512
    const int warp = tid >> 5, lane = tid & 31;
    __shared__ float au[KKA];
    __shared__ float accv[32][17], acc2[32][17];
    __shared__ float accr[32];
    __shared__ float mu[32][17], i2s[32][17], sigs[32][17];
    __shared__ float lsum2[32], loga[32], aouts[32], rsum_sh[32];
    __shared__ float wred[16];
    __shared__ float sau_sh;

    for (int i = tid; i < KKA; i += 512) au[i] = g_au[bl][i];
    __syncthreads();
    {
        float s = (tid < KKA) ? au[tid] : 0.f;
#pragma unroll
        for (int o = 16; o; o >>= 1) s += __shfl_xor_sync(~0u, s, o);
        if (lane == 0) wred[warp] = s;
        __syncthreads();
        if (tid == 0) { float t = 0.f; for (int i = 0; i < 16; ++i) t += wred[i]; sau_sh = t; }
        __syncthreads();
    }
    const float* __restrict__ vb = &g_v[bl][0][0][0];   // [k][p][b], stride 512 per k
    const int b = tid >> 4, q = tid & 15;
    const float LOG_LN2PI = logf(LN2PI);

    // ---- finalize iter 0 from votes-kernel stats (uniform r) ----
    {
        float rs = sau_sh * (1.f / 32.f);
        float iv = 1.f / (rs + EPSV);
        float m  = g_pass0[bl][0][tid] * (1.f / 32.f) * iv;
        float sg = g_pass0[bl][1][tid] * (1.f / 32.f) * iv - m * m + EPSV;
        mu[b][q] = m; sigs[b][q] = sg; i2s[b][q] = 0.5f / sg;
        if (tid < 32) rsum_sh[tid] = rs;
    }
    __syncthreads();
    if (tid < 32) {
        float ls = 0.f;
#pragma unroll
        for (int j = 0; j < 16; ++j) ls += logf(sigs[tid][j]);
        float cost = rsum_sh[tid] * (16.f * beta_u[tid] + 0.5f * ls);
        float z = 5.0e-4f * (beta_a[tid] - cost);
        float ao = 1.f / (1.f + expf(-z));
        aouts[tid] = ao; loga[tid] = logf(ao);
        lsum2[tid] = ls + 16.f * LOG_LN2PI;
    }
    __syncthreads();

    // ---- fused passes: e-step(it) + stats(it+1), coalesced scalar v loads ----
#pragma unroll 1
    for (int it = 0; it < 2; ++it) {
        for (int i = tid; i < 32 * 17; i += 512) { (&accv[0][0])[i] = 0.f; (&acc2[0][0])[i] = 0.f; }
        if (tid < 32) accr[tid] = 0.f;
        __syncthreads();
        float A[16], TMA[16];
        float Kc;
        {
            float cst = 0.f;
#pragma unroll
            for (int j = 0; j < 16; ++j) {
                float m = mu[lane][j], ai = i2s[lane][j];
                A[j] = ai; TMA[j] = 2.f * m * ai;
                cst += m * m * ai;
            }
            Kc = loga[lane] - 0.5f * lsum2[lane] - cst;
        }
        float av[16], a2[16], ar = 0.f;
#pragma unroll
        for (int j = 0; j < 16; ++j) { av[j] = 0.f; a2[j] = 0.f; }

        // prologue prefetch (k = warp): 16 coalesced LDG.32 (lane = b, 1 line each)
        float nx[16];
        {
            const float* vp = vb + warp * 512 + lane;
#pragma unroll
            for (int j = 0; j < 16; ++j) nx[j] = vp[j * 32];
        }
#pragma unroll 1
        for (int k = warp; k < KKA; k += 16) {
            float cu[16];
#pragma unroll
            for (int j = 0; j < 16; ++j) cu[j] = nx[j];
            int kn = k + 16;
            if (kn < KKA) {
                const float* vp = vb + kn * 512 + lane;
#pragma unroll
                for (int j = 0; j < 16; ++j) nx[j] = vp[j * 32];
            }
            // 4 independent partial chains (tree), then combine
            float s0, s1, s2, s3;
            s0  = cu[0] * fmaf(-A[0],  cu[0],  TMA[0]);
            s0  = fmaf(cu[1],  fmaf(-A[1],  cu[1],  TMA[1]),  s0);
            s0  = fmaf(cu[2],  fmaf(-A[2],  cu[2],  TMA[2]),  s0);
            s0  = fmaf(cu[3],  fmaf(-A[3],  cu[3],  TMA[3]),  s0);
            s1  = cu[4] * fmaf(-A[4],  cu[4],  TMA[4]);
            s1  = fmaf(cu[5],  fmaf(-A[5],  cu[5],  TMA[5]),  s1);
            s1  = fmaf(cu[6],  fmaf(-A[6],  cu[6],  TMA[6]),  s1);
            s1  = fmaf(cu[7],  fmaf(-A[7],  cu[7],  TMA[7]),  s1);
            s2  = cu[8] * fmaf(-A[8],  cu[8],  TMA[8]);
            s2  = fmaf(cu[9],  fmaf(-A[9],  cu[9],  TMA[9]),  s2);
            s2  = fmaf(cu[10], fmaf(-A[10], cu[10], TMA[10]), s2);
            s2  = fmaf(cu[11], fmaf(-A[11], cu[11], TMA[11]), s2);
            s3  = cu[12] * fmaf(-A[12], cu[12], TMA[12]);
            s3  = fmaf(cu[13], fmaf(-A[13], cu[13], TMA[13]), s3);
            s3  = fmaf(cu[14], fmaf(-A[14], cu[14], TMA[14]), s3);
            s3  = fmaf(cu[15], fmaf(-A[15], cu[15], TMA[15]), s3);
            float lnap = Kc + ((s0 + s1) + (s2 + s3));
            float mx = warp_redux_max_f32(lnap);
            float e = __expf(lnap - mx);
            float se = e;
#pragma unroll
            for (int o = 16; o; o >>= 1) se += __shfl_xor_sync(~0u, se, o);
            float c = __fdividef(e, se) * au[k];
            ar += c;
#pragma unroll
            for (int j = 0; j < 16; ++j) {
                float t = c * cu[j];
                av[j] += t;
                a2[j] = fmaf(t, cu[j], a2[j]);
            }
        }
#pragma unroll
        for (int j = 0; j < 16; ++j) {
            atomicAdd(&accv[lane][j], av[j]);
            atomicAdd(&acc2[lane][j], a2[j]);
        }
        atomicAdd(&accr[lane], ar);
        __syncthreads();
        {
            float rs = accr[b];
            float iv = 1.f / (rs + EPSV);
            float m  = accv[b][q] * iv;
            float sg = acc2[b][q] * iv - m * m + EPSV;
            mu[b][q] = m; sigs[b][q] = sg; i2s[b][q] = 0.5f / sg;
            if (tid < 32) rsum_sh[tid] = accr[tid];
        }
        __syncthreads();
        if (tid < 32) {
            float ls = 0.f;
#pragma unroll
            for (int j = 0; j < 16; ++j) ls += logf(sigs[tid][j]);
            float cost = rsum_sh[tid] * (16.f * beta_u[tid] + 0.5f * ls);
            float lam = (it == 0) ? 9.75e-4f : 1.42625e-3f;
            float z = lam * (beta_a[tid] - cost);
            float ao = 1.f / (1.f + expf(-z));
            aouts[tid] = ao; loga[tid] = logf(ao);
            lsum2[tid] = ls + 16.f * LOG_LN2PI;
        }
        __syncthreads();
    }
    // outputs: a_fin [BATCH][32][7][7] then pose_out [BATCH][512][7][7]
    int batch = bl / L, pos = bl - batch * L;
    if (tid < 32) out[(batch * 32 + tid) * L + pos] = aouts[tid];
    out[BATCH * 32 * L + (batch * 512 + tid) * L + pos] = mu[b][q];
}

// ---------------- launch ----------------
extern "C" void kernel_launch(void* const* d_in, const int* in_sizes, int n_in,
                              void* d_out, int out_size) {
    const float* a_in   = (const float*)d_in[0];
    const float* pose   = (const float*)d_in[1];
    const float* mposew = (const float*)d_in[2];
    const float* mposeb = (const float*)d_in[3];
    const float* freqw  = (const float*)d_in[4];
    const float* beta_u = (const float*)d_in[9];
    const float* beta_a = (const float*)d_in[10];
    float* out = (float*)d_out;

    k_build_h<<<16, KKA>>>(freqw);
    k_setup<<<128 + (16 * KKA * KKA + 255) / 256, 256>>>(pose, a_in);
    k_gemm<<<dim3(NPAD / 64, GM / 128), 256>>>();
    k_votes<<<dim3(BL, 18), 512>>>(mposew, mposeb);
    k_em<<<BL, 512>>>(beta_u, beta_a, out);
}

// round 16
// speedup vs baseline: 1.2249x; 1.2249x over previous
#include <cuda_runtime.h>
#include <cuda_fp16.h>
#include <mma.h>
#include <math.h>

using namespace nvcuda;

// Problem constants
#define BATCH 4
#define AC 32
#define BC 32
#define PS 16
#define KK 9
#define KKA 288
#define H 14
#define OH 7
#define L 49
#define BL 196
#define NPP 3136
#define NPAD 3200
#define NBLK 200         // NPAD/16 column blocks
#define GM 4608          // 16 * 288 fused GEMM M
#define EPSV 1e-12f
#define LN2PI 1.8378770664093453f

// ---------------- device scratch ----------------
__device__ float g_h[16][KKA];
__device__ float g_S[16];
__device__ __half g_Ch[GM][KKA];        // fp16 circulant rows, row = k*16+pf
__device__ float g_PU[KKA][NPAD];       // fp32 unfolded pose
__device__ __half g_PUh[KKA][NPAD];     // fp16 copy for GEMM
__device__ float g_U2[KKA][NBLK][256];  // correction, blocked [k][bl][pf][pp]
__device__ float g_v[BL][KKA][BC][PS];  // votes, fp32 [bl][k][b][p]
__device__ float g_au[BL][KKA];
__device__ float g_pass0[BL][2][512];   // pass-0 stats

__device__ __forceinline__ void cp16(void* smem_dst, const void* gsrc) {
    unsigned s = (unsigned)__cvta_generic_to_shared(smem_dst);
    asm volatile("cp.async.cg.shared.global [%0], [%1], 16;\n" :: "r"(s), "l"(gsrc));
}
#define CP_COMMIT() asm volatile("cp.async.commit_group;\n")
#define CP_WAIT(n)  asm volatile("cp.async.wait_group %0;\n" :: "n"(n))

// f32 warp max via integer redux (monotonic key mapping; valid for non-NaN).
__device__ __forceinline__ float warp_redux_max_f32(float x) {
    unsigned u = __float_as_uint(x);
    unsigned key = (u & 0x80000000u) ? ~u : (u | 0x80000000u);
    unsigned r;
    asm volatile("redux.sync.max.u32 %0, %1, 0xffffffff;" : "=r"(r) : "r"(key));
    unsigned v = (r & 0x80000000u) ? (r & 0x7fffffffu) : ~r;
    return __uint_as_float(v);
}

// ---------------- kernel 0: circulant kernels h_p, S_p ----------------
__global__ void k_build_h(const float* __restrict__ fw) {
    int p = blockIdx.x;          // 0..15
    int d = threadIdx.x;         // 0..287
    float wr0   = fw[(0 * 16 + p) * 2];
    float wr144 = fw[(144 * 16 + p) * 2];
    float s = 0.f;
    for (int k = 1; k <= 143; ++k) {
        float wr = fw[(k * 16 + p) * 2];
        float wi = fw[(k * 16 + p) * 2 + 1];
        int md = (k * d) % KKA;
        float x = (float)md * (1.0f / 144.0f);
        float sn, cs;
        sincospif(x, &sn, &cs);
        s += wr * cs - wi * sn;
    }
    float h = (wr0 + ((d & 1) ? -wr144 : wr144) + 2.f * s) * (1.0f / (float)KKA);
    g_h[p][d] = h;
    __shared__ float red[KKA];
    red[d] = h;
    __syncthreads();
    if (d == 0) {
        float t = 0.f;
        for (int i = 0; i < KKA; ++i) t += red[i];
        g_S[p] = t;
    }
}

// ---------------- kernel 1: merged setup ----------------
__global__ void k_setup(const float* __restrict__ pose, const float* __restrict__ a_in) {
    __shared__ float tile[16][197];
    __shared__ float ta[196];
    const int tid = threadIdx.x;         // 256

    if (blockIdx.x >= 128) {
        int idx = (blockIdx.x - 128) * 256 + tid;
        if (idx < BL * 2 * 512) ((float*)g_pass0)[idx] = 0.f;
        if (idx < 16 * KKA * KKA) {
            int row = idx / KKA;          // 0..4607 = k*16+pf
            int m = idx - row * KKA;
            int k = row >> 4, pf = row & 15;
            int d = k - m; if (d < 0) d += KKA;
            g_Ch[row][m] = __float2half(g_h[pf][d]);
        }
        return;
    }
    const int blk = blockIdx.x;          // 0..127
    const int batch = blk >> 5;
    const int a = blk & 31;

    const float* src = pose + (size_t)(batch * (AC * PS) + a * PS) * 196;
    for (int i = tid; i < 16 * 196; i += 256) {
        int pp = i / 196, r = i - pp * 196;
        tile[pp][r] = src[pp * 196 + r];
    }
    for (int i = tid; i < 196; i += 256)
        ta[i] = a_in[(batch * AC + a) * 196 + i];
    __syncthreads();

    for (int i = tid; i < 9 * 49 * 16; i += 256) {
        int pp = i & 15;
        int rest = i >> 4;
        int pos = rest % 49;
        int kk = rest / 49;
        int y = pos / 7, x = pos - y * 7;
        int iy = 2 * y - 1 + kk / 3;
        int ix = 2 * x - 1 + (kk - (kk / 3) * 3);
        bool ok = (iy >= 0) & (iy < H) & (ix >= 0) & (ix < H);
        float v = ok ? tile[pp][iy * 14 + ix] : 0.f;
        int m = kk * 32 + a;
        int col = (batch * 49 + pos) * 16 + pp;
        g_PU[m][col] = v;
        g_PUh[m][col] = __float2half(v);
        if (pp == 0)
            g_au[batch * 49 + pos][m] = ok ? ta[iy * 14 + ix] : 0.f;
    }
}

// ---------------- kernel 3: fp16 tensor GEMM, blocked epilogue ----------------
#define LDA 40
#define LDB 72
__global__ void k_gemm() {
    __shared__ __half sA[2][128 * LDA];
    __shared__ __half sB[2][32 * LDB];
    const int tid = threadIdx.x;
    const int row0 = blockIdx.y * 128;
    const int col0 = blockIdx.x * 64;
    const __half* Ag = &g_Ch[0][0];
    const __half* Bg = &g_PUh[0][0];
    const int wm = (tid >> 5) & 3;
    const int wn = tid >> 7;

    wmma::fragment<wmma::accumulator, 16, 16, 16, float> acc[2][2];
#pragma unroll
    for (int i = 0; i < 2; ++i)
#pragma unroll
        for (int j = 0; j < 2; ++j) wmma::fill_fragment(acc[i][j], 0.f);

    {
#pragma unroll
        for (int t = tid; t < 512; t += 256) {
            int r = t >> 2, c = t & 3;
            cp16(&sA[0][r * LDA + c * 8], Ag + (row0 + r) * KKA + c * 8);
        }
        int r = tid >> 3, c = tid & 7;
        cp16(&sB[0][r * LDB + c * 8], Bg + r * NPAD + col0 + c * 8);
        CP_COMMIT();
    }
    int cur = 0;
    for (int kt = 0; kt < 9; ++kt) {
        if (kt < 8) {
            int k0 = (kt + 1) * 32;
            int nxt = cur ^ 1;
#pragma unroll
            for (int t = tid; t < 512; t += 256) {
                int r = t >> 2, c = t & 3;
                cp16(&sA[nxt][r * LDA + c * 8], Ag + (row0 + r) * KKA + k0 + c * 8);
            }
            int r = tid >> 3, c = tid & 7;
            cp16(&sB[nxt][r * LDB + c * 8], Bg + (k0 + r) * NPAD + col0 + c * 8);
            CP_COMMIT();
            CP_WAIT(1);
        } else {
            CP_WAIT(0);
        }
        __syncthreads();
#pragma unroll
        for (int ks = 0; ks < 2; ++ks) {
            wmma::fragment<wmma::matrix_a, 16, 16, 16, __half, wmma::row_major> a0, a1;
            wmma::fragment<wmma::matrix_b, 16, 16, 16, __half, wmma::row_major> b0, b1;
            wmma::load_matrix_sync(a0, &sA[cur][(wm * 32) * LDA + ks * 16], LDA);
            wmma::load_matrix_sync(a1, &sA[cur][(wm * 32 + 16) * LDA + ks * 16], LDA);
            wmma::load_matrix_sync(b0, &sB[cur][(ks * 16) * LDB + wn * 32], LDB);
            wmma::load_matrix_sync(b1, &sB[cur][(ks * 16) * LDB + wn * 32 + 16], LDB);
            wmma::mma_sync(acc[0][0], a0, b0, acc[0][0]);
            wmma::mma_sync(acc[0][1], a0, b1, acc[0][1]);
            wmma::mma_sync(acc[1][0], a1, b0, acc[1][0]);
            wmma::mma_sync(acc[1][1], a1, b1, acc[1][1]);
        }
        __syncthreads();
        cur ^= 1;
    }
    // blocked epilogue: each 16x16 tile = (k fixed, blk16 fixed, pf x pp) -> ld=16
#pragma unroll
    for (int i = 0; i < 2; ++i)
#pragma unroll
        for (int j = 0; j < 2; ++j) {
            int rt = row0 + wm * 32 + i * 16;     // = k*16
            int ct = col0 + wn * 32 + j * 16;     // = blk16*16
            int k = rt >> 4;
            int blb = ct >> 4;
            wmma::store_matrix_sync(&g_U2[k][blb][0], acc[i][j], 16, wmma::mem_row_major);
        }
}

// ---------------- kernel 4: votes + pass-0 stats, 2 bl per block ------
// grid (98, 18). thread map: tid = kh*256 + bb*16 + p (o0 = tid&255, coalesced W).
__global__ void __launch_bounds__(512) k_votes(const float* __restrict__ W,
                                               const float* __restrict__ mb) {
    const int bl0 = blockIdx.x * 2;
    const int k0 = blockIdx.y * 16;
    const int tid = threadIdx.x;      // 512
    __shared__ __align__(16) float Usf[16][16][20];   // [k][pf][pp] pad 20
    __shared__ float sau[16];

    const int kh = tid >> 8;          // 0..1 (k-half)
    const int rr = tid & 255;
    const int bb = rr >> 4;           // 0..15
    const int p  = rr & 15;
    const int o0 = bb * 16 + p;             // = rr (coalesced)
    const int o1 = (bb + 16) * 16 + p;

    float w0[16], w1[16];
    {
        const float4* wv0 = (const float4*)(W + o0 * 16);
        const float4* wv1 = (const float4*)(W + o1 * 16);
#pragma unroll
        for (int f = 0; f < 4; ++f) {
            float4 a = wv0[f], c = wv1[f];
            w0[f * 4 + 0] = a.x; w0[f * 4 + 1] = a.y; w0[f * 4 + 2] = a.z; w0[f * 4 + 3] = a.w;
            w1[f * 4 + 0] = c.x; w1[f * 4 + 1] = c.y; w1[f * 4 + 2] = c.z; w1[f * 4 + 3] = c.w;
        }
    }
    const float gs = 1.f + g_S[p];
    const float sb0 = mb[o0] * gs;
    const float sb1 = mb[o1] * gs;

#pragma unroll 1
    for (int half = 0; half < 2; ++half) {
        const int bl = bl0 + half;
        const int col = bl * PS;
        if (half) __syncthreads();          // protect Usf reuse
        if (tid < 16) sau[tid] = g_au[bl][k0 + tid];
        // stage 16 k x 16 pf x 16 pp: y = U2 (read-once: ldcs) + PU
#pragma unroll
        for (int i = tid; i < 1024; i += 512) {
            int f = i & 3;
            int pf = (i >> 2) & 15;
            int k = i >> 6;               // 0..15
            float4 u4 = __ldcs((const float4*)&g_U2[k0 + k][bl][pf * 16 + f * 4]);
            float4 r4 = *(const float4*)&g_PU[k0 + k][col + f * 4];
            float4 y;
            y.x = u4.x + r4.x; y.y = u4.y + r4.y;
            y.z = u4.z + r4.z; y.w = u4.w + r4.w;
            *(float4*)&Usf[k][pf][f * 4] = y;
        }
        __syncthreads();
        float aV0 = 0.f, aQ0 = 0.f, aV1 = 0.f, aQ1 = 0.f;
#pragma unroll
        for (int kk = 0; kk < 8; ++kk) {
            int k = kh * 8 + kk;
            const float4* yr = (const float4*)&Usf[k][p][0];
            float4 y0 = yr[0], y1 = yr[1], y2 = yr[2], y3 = yr[3];
            float s0 = sb0, s1 = sb1;
            s0 += y0.x * w0[0]  + y0.y * w0[1]  + y0.z * w0[2]  + y0.w * w0[3];
            s1 += y0.x * w1[0]  + y0.y * w1[1]  + y0.z * w1[2]  + y0.w * w1[3];
            s0 += y1.x * w0[4]  + y1.y * w0[5]  + y1.z * w0[6]  + y1.w * w0[7];
            s1 += y1.x * w1[4]  + y1.y * w1[5]  + y1.z * w1[6]  + y1.w * w1[7];
            s0 += y2.x * w0[8]  + y2.y * w0[9]  + y2.z * w0[10] + y2.w * w0[11];
            s1 += y2.x * w1[8]  + y2.y * w1[9]  + y2.z * w1[10] + y2.w * w1[11];
            s0 += y3.x * w0[12] + y3.y * w0[13] + y3.z * w0[14] + y3.w * w0[15];
            s1 += y3.x * w1[12] + y3.y * w1[13] + y3.z * w1[14] + y3.w * w1[15];
            g_v[bl][k0 + k][bb][p] = s0;
            g_v[bl][k0 + k][bb + 16][p] = s1;
            float auk = sau[k];
            aV0 += auk * s0; aQ0 += auk * s0 * s0;
            aV1 += auk * s1; aQ1 += auk * s1 * s1;
        }
        atomicAdd(&g_pass0[bl][0][o0], aV0);
        atomicAdd(&g_pass0[bl][1][o0], aQ0);
        atomicAdd(&g_pass0[bl][0][o1], aV1);
        atomicAdd(&g_pass0[bl][1][o1], aQ1);
    }
}

// ---------------- kernel 5: fused EM routing (R14 version, unchanged) ----------
__global__ void __launch_bounds__(512) k_em(const float* __restrict__ beta_u,
                                            const float* __restrict__ beta_a,
                                            float* __restrict__ out) {
    const int bl = blockIdx.x;        // 196
    const int tid = threadIdx.x;      // 512
    const int warp = tid >> 5, lane = tid & 31;
    __shared__ float au[KKA];
    __shared__ float accv[32][17], acc2[32][17];
    __shared__ float accr[32];
    __shared__ float mu[32][17], i2s[32][17], sigs[32][17];
    __shared__ float lsum2[32], loga[32], aouts[32], rsum_sh[32];
    __shared__ float wred[16];
    __shared__ float sau_sh;

    for (int i = tid; i < KKA; i += 512) au[i] = g_au[bl][i];
    __syncthreads();
    {
        float s = (tid < KKA) ? au[tid] : 0.f;
#pragma unroll
        for (int o = 16; o; o >>= 1) s += __shfl_xor_sync(~0u, s, o);
        if (lane == 0) wred[warp] = s;
        __syncthreads();
        if (tid == 0) { float t = 0.f; for (int i = 0; i < 16; ++i) t += wred[i]; sau_sh = t; }
        __syncthreads();
    }
    const float* __restrict__ vb = &g_v[bl][0][0][0];
    const int b = tid >> 4, q = tid & 15;
    const float LOG_LN2PI = logf(LN2PI);

    // ---- finalize iter 0 from votes-kernel stats (uniform r) ----
    {
        float rs = sau_sh * (1.f / 32.f);
        float iv = 1.f / (rs + EPSV);
        float m  = g_pass0[bl][0][tid] * (1.f / 32.f) * iv;
        float sg = g_pass0[bl][1][tid] * (1.f / 32.f) * iv - m * m + EPSV;
        mu[b][q] = m; sigs[b][q] = sg; i2s[b][q] = 0.5f / sg;
        if (tid < 32) rsum_sh[tid] = rs;
    }
    __syncthreads();
    if (tid < 32) {
        float ls = 0.f;
#pragma unroll
        for (int j = 0; j < 16; ++j) ls += logf(sigs[tid][j]);
        float cost = rsum_sh[tid] * (16.f * beta_u[tid] + 0.5f * ls);
        float z = 5.0e-4f * (beta_a[tid] - cost);
        float ao = 1.f / (1.f + expf(-z));
        aouts[tid] = ao; loga[tid] = logf(ao);
        lsum2[tid] = ls + 16.f * LOG_LN2PI;
    }
    __syncthreads();

    // ---- fused passes: e-step(it) + stats(it+1), prefetched v stream ----
#pragma unroll 1
    for (int it = 0; it < 2; ++it) {
        for (int i = tid; i < 32 * 17; i += 512) { (&accv[0][0])[i] = 0.f; (&acc2[0][0])[i] = 0.f; }
        if (tid < 32) accr[tid] = 0.f;
        __syncthreads();
        float A[16], TMA[16];
        float Kc;
        {
            float cst = 0.f;
#pragma unroll
            for (int j = 0; j < 16; ++j) {
                float m = mu[lane][j], ai = i2s[lane][j];
                A[j] = ai; TMA[j] = 2.f * m * ai;
                cst += m * m * ai;
            }
            Kc = loga[lane] - 0.5f * lsum2[lane] - cst;
        }
        float av[16], a2[16], ar = 0.f;
#pragma unroll
        for (int j = 0; j < 16; ++j) { av[j] = 0.f; a2[j] = 0.f; }

        // prologue prefetch (k = warp)
        float4 n0, n1, n2, n3;
        {
            const float4* vp = (const float4*)(vb + (warp * 32 + lane) * 16);
            n0 = vp[0]; n1 = vp[1]; n2 = vp[2]; n3 = vp[3];
        }
#pragma unroll 1
        for (int k = warp; k < KKA; k += 16) {
            float4 q0 = n0, q1 = n1, q2 = n2, q3 = n3;
            int kn = k + 16;
            if (kn < KKA) {
                const float4* vp = (const float4*)(vb + (kn * 32 + lane) * 16);
                n0 = vp[0]; n1 = vp[1]; n2 = vp[2]; n3 = vp[3];
            }
            // 4 independent partial chains (tree), then combine
            float s0, s1, s2, s3;
            s0  = q0.x * fmaf(-A[0],  q0.x, TMA[0]);
            s0  = fmaf(q0.y, fmaf(-A[1],  q0.y, TMA[1]),  s0);
            s0  = fmaf(q0.z, fmaf(-A[2],  q0.z, TMA[2]),  s0);
            s0  = fmaf(q0.w, fmaf(-A[3],  q0.w, TMA[3]),  s0);
            s1  = q1.x * fmaf(-A[4],  q1.x, TMA[4]);
            s1  = fmaf(q1.y, fmaf(-A[5],  q1.y, TMA[5]),  s1);
            s1  = fmaf(q1.z, fmaf(-A[6],  q1.z, TMA[6]),  s1);
            s1  = fmaf(q1.w, fmaf(-A[7],  q1.w, TMA[7]),  s1);
            s2  = q2.x * fmaf(-A[8],  q2.x, TMA[8]);
            s2  = fmaf(q2.y, fmaf(-A[9],  q2.y, TMA[9]),  s2);
            s2  = fmaf(q2.z, fmaf(-A[10], q2.z, TMA[10]), s2);
            s2  = fmaf(q2.w, fmaf(-A[11], q2.w, TMA[11]), s2);
            s3  = q3.x * fmaf(-A[12], q3.x, TMA[12]);
            s3  = fmaf(q3.y, fmaf(-A[13], q3.y, TMA[13]), s3);
            s3  = fmaf(q3.z, fmaf(-A[14], q3.z, TMA[14]), s3);
            s3  = fmaf(q3.w, fmaf(-A[15], q3.w, TMA[15]), s3);
            float lnap = Kc + ((s0 + s1) + (s2 + s3));
            float mx = warp_redux_max_f32(lnap);
            float e = __expf(lnap - mx);
            float se = e;
#pragma unroll
            for (int o = 16; o; o >>= 1) se += __shfl_xor_sync(~0u, se, o);
            float c = __fdividef(e, se) * au[k];
            ar += c;
            float t;
            t = c * q0.x; av[0]  += t; a2[0]  = fmaf(t, q0.x, a2[0]);
            t = c * q0.y; av[1]  += t; a2[1]  = fmaf(t, q0.y, a2[1]);
            t = c * q0.z; av[2]  += t; a2[2]  = fmaf(t, q0.z, a2[2]);
            t = c * q0.w; av[3]  += t; a2[3]  = fmaf(t, q0.w, a2[3]);
            t = c * q1.x; av[4]  += t; a2[4]  = fmaf(t, q1.x, a2[4]);
            t = c * q1.y; av[5]  += t; a2[5]  = fmaf(t, q1.y, a2[5]);
            t = c * q1.z; av[6]  += t; a2[6]  = fmaf(t, q1.z, a2[6]);
            t = c * q1.w; av[7]  += t; a2[7]  = fmaf(t, q1.w, a2[7]);
            t = c * q2.x; av[8]  += t; a2[8]  = fmaf(t, q2.x, a2[8]);
            t = c * q2.y; av[9]  += t; a2[9]  = fmaf(t, q2.y, a2[9]);
            t = c * q2.z; av[10] += t; a2[10] = fmaf(t, q2.z, a2[10]);
            t = c * q2.w; av[11] += t; a2[11] = fmaf(t, q2.w, a2[11]);
            t = c * q3.x; av[12] += t; a2[12] = fmaf(t, q3.x, a2[12]);
            t = c * q3.y; av[13] += t; a2[13] = fmaf(t, q3.y, a2[13]);
            t = c * q3.z; av[14] += t; a2[14] = fmaf(t, q3.z, a2[14]);
            t = c * q3.w; av[15] += t; a2[15] = fmaf(t, q3.w, a2[15]);
        }
#pragma unroll
        for (int j = 0; j < 16; ++j) {
            atomicAdd(&accv[lane][j], av[j]);
            atomicAdd(&acc2[lane][j], a2[j]);
        }
        atomicAdd(&accr[lane], ar);
        __syncthreads();
        {
            float rs = accr[b];
            float iv = 1.f / (rs + EPSV);
            float m  = accv[b][q] * iv;
            float sg = acc2[b][q] * iv - m * m + EPSV;
            mu[b][q] = m; sigs[b][q] = sg; i2s[b][q] = 0.5f / sg;
            if (tid < 32) rsum_sh[tid] = accr[tid];
        }
        __syncthreads();
        if (tid < 32) {
            float ls = 0.f;
#pragma unroll
            for (int j = 0; j < 16; ++j) ls += logf(sigs[tid][j]);
            float cost = rsum_sh[tid] * (16.f * beta_u[tid] + 0.5f * ls);
            float lam = (it == 0) ? 9.75e-4f : 1.42625e-3f;
            float z = lam * (beta_a[tid] - cost);
            float ao = 1.f / (1.f + expf(-z));
            aouts[tid] = ao; loga[tid] = logf(ao);
            lsum2[tid] = ls + 16.f * LOG_LN2PI;
        }
        __syncthreads();
    }
    // outputs: a_fin [BATCH][32][7][7] then pose_out [BATCH][512][7][7]
    int batch = bl / L, pos = bl - batch * L;
    if (tid < 32) out[(batch * 32 + tid) * L + pos] = aouts[tid];
    out[BATCH * 32 * L + (batch * 512 + tid) * L + pos] = mu[b][q];
}

// ---------------- launch ----------------
extern "C" void kernel_launch(void* const* d_in, const int* in_sizes, int n_in,
                              void* d_out, int out_size) {
    const float* a_in   = (const float*)d_in[0];
    const float* pose   = (const float*)d_in[1];
    const float* mposew = (const float*)d_in[2];
    const float* mposeb = (const float*)d_in[3];
    const float* freqw  = (const float*)d_in[4];
    const float* beta_u = (const float*)d_in[9];
    const float* beta_a = (const float*)d_in[10];
    float* out = (float*)d_out;

    k_build_h<<<16, KKA>>>(freqw);
    k_setup<<<128 + (16 * KKA * KKA + 255) / 256, 256>>>(pose, a_in);
    k_gemm<<<dim3(NPAD / 64, GM / 128), 256>>>();
    k_votes<<<dim3(BL / 2, 18), 512>>>(mposew, mposeb);
    k_em<<<BL, 512>>>(beta_u, beta_a, out);
}

// round 17
// speedup vs baseline: 1.2408x; 1.0129x over previous
#include <cuda_runtime.h>
#include <cuda_fp16.h>
#include <mma.h>
#include <math.h>

using namespace nvcuda;

// Problem constants
#define BATCH 4
#define AC 32
#define BC 32
#define PS 16
#define KK 9
#define KKA 288
#define H 14
#define OH 7
#define L 49
#define BL 196
#define NPP 3136
#define NPAD 3200
#define NBLK 200         // NPAD/16 column blocks
#define GM 4608          // 16 * 288 fused GEMM M
#define EPSV 1e-12f
#define LN2PI 1.8378770664093453f

// ---------------- device scratch ----------------
__device__ float g_h[16][KKA];
__device__ float g_S[16];
__device__ __half g_Ch[GM][KKA];        // fp16 circulant rows, row = k*16+pf
__device__ float g_PU[KKA][NPAD];       // fp32 unfolded pose
__device__ __half g_PUh[KKA][NPAD];     // fp16 copy for GEMM
__device__ __half g_U2h[KKA][NBLK][256];// fp16 correction, blocked [k][bl][pf][pp]  29.5 MB
__device__ float g_v[BL][KKA][BC][PS];  // votes, fp32 [bl][k][b][p]
__device__ float g_au[BL][KKA];
__device__ float g_pass0[BL][2][512];   // pass-0 stats

__device__ __forceinline__ void cp16(void* smem_dst, const void* gsrc) {
    unsigned s = (unsigned)__cvta_generic_to_shared(smem_dst);
    asm volatile("cp.async.cg.shared.global [%0], [%1], 16;\n" :: "r"(s), "l"(gsrc));
}
#define CP_COMMIT() asm volatile("cp.async.commit_group;\n")
#define CP_WAIT(n)  asm volatile("cp.async.wait_group %0;\n" :: "n"(n))

// f32 warp max via integer redux (monotonic key mapping; valid for non-NaN).
__device__ __forceinline__ float warp_redux_max_f32(float x) {
    unsigned u = __float_as_uint(x);
    unsigned key = (u & 0x80000000u) ? ~u : (u | 0x80000000u);
    unsigned r;
    asm volatile("redux.sync.max.u32 %0, %1, 0xffffffff;" : "=r"(r) : "r"(key));
    unsigned v = (r & 0x80000000u) ? (r & 0x7fffffffu) : ~r;
    return __uint_as_float(v);
}

// ---------------- kernel 0: circulant kernels h_p, S_p ----------------
__global__ void k_build_h(const float* __restrict__ fw) {
    int p = blockIdx.x;          // 0..15
    int d = threadIdx.x;         // 0..287
    float wr0   = fw[(0 * 16 + p) * 2];
    float wr144 = fw[(144 * 16 + p) * 2];
    float s = 0.f;
    for (int k = 1; k <= 143; ++k) {
        float wr = fw[(k * 16 + p) * 2];
        float wi = fw[(k * 16 + p) * 2 + 1];
        int md = (k * d) % KKA;
        float x = (float)md * (1.0f / 144.0f);
        float sn, cs;
        sincospif(x, &sn, &cs);
        s += wr * cs - wi * sn;
    }
    float h = (wr0 + ((d & 1) ? -wr144 : wr144) + 2.f * s) * (1.0f / (float)KKA);
    g_h[p][d] = h;
    __shared__ float red[KKA];
    red[d] = h;
    __syncthreads();
    if (d == 0) {
        float t = 0.f;
        for (int i = 0; i < KKA; ++i) t += red[i];
        g_S[p] = t;
    }
}

// ---------------- kernel 1: merged setup ----------------
__global__ void k_setup(const float* __restrict__ pose, const float* __restrict__ a_in) {
    __shared__ float tile[16][197];
    __shared__ float ta[196];
    const int tid = threadIdx.x;         // 256

    if (blockIdx.x >= 128) {
        int idx = (blockIdx.x - 128) * 256 + tid;
        if (idx < BL * 2 * 512) ((float*)g_pass0)[idx] = 0.f;
        if (idx < 16 * KKA * KKA) {
            int row = idx / KKA;          // 0..4607 = k*16+pf
            int m = idx - row * KKA;
            int k = row >> 4, pf = row & 15;
            int d = k - m; if (d < 0) d += KKA;
            g_Ch[row][m] = __float2half(g_h[pf][d]);
        }
        return;
    }
    const int blk = blockIdx.x;          // 0..127
    const int batch = blk >> 5;
    const int a = blk & 31;

    const float* src = pose + (size_t)(batch * (AC * PS) + a * PS) * 196;
    for (int i = tid; i < 16 * 196; i += 256) {
        int pp = i / 196, r = i - pp * 196;
        tile[pp][r] = src[pp * 196 + r];
    }
    for (int i = tid; i < 196; i += 256)
        ta[i] = a_in[(batch * AC + a) * 196 + i];
    __syncthreads();

    for (int i = tid; i < 9 * 49 * 16; i += 256) {
        int pp = i & 15;
        int rest = i >> 4;
        int pos = rest % 49;
        int kk = rest / 49;
        int y = pos / 7, x = pos - y * 7;
        int iy = 2 * y - 1 + kk / 3;
        int ix = 2 * x - 1 + (kk - (kk / 3) * 3);
        bool ok = (iy >= 0) & (iy < H) & (ix >= 0) & (ix < H);
        float v = ok ? tile[pp][iy * 14 + ix] : 0.f;
        int m = kk * 32 + a;
        int col = (batch * 49 + pos) * 16 + pp;
        g_PU[m][col] = v;
        g_PUh[m][col] = __float2half(v);
        if (pp == 0)
            g_au[batch * 49 + pos][m] = ok ? ta[iy * 14 + ix] : 0.f;
    }
}

// ---------------- kernel 3: fp16 tensor GEMM, blocked fp16 epilogue ----------------
#define LDA 40
#define LDB 72
__global__ void k_gemm() {
    __shared__ __half sA[2][128 * LDA];
    __shared__ __half sB[2][32 * LDB];
    __shared__ float cbuf[8][256];       // per-warp epilogue bounce, 8 KB
    const int tid = threadIdx.x;
    const int row0 = blockIdx.y * 128;
    const int col0 = blockIdx.x * 64;
    const __half* Ag = &g_Ch[0][0];
    const __half* Bg = &g_PUh[0][0];
    const int wid = tid >> 5, lane = tid & 31;
    const int wm = wid & 3;
    const int wn = wid >> 2;

    wmma::fragment<wmma::accumulator, 16, 16, 16, float> acc[2][2];
#pragma unroll
    for (int i = 0; i < 2; ++i)
#pragma unroll
        for (int j = 0; j < 2; ++j) wmma::fill_fragment(acc[i][j], 0.f);

    {
#pragma unroll
        for (int t = tid; t < 512; t += 256) {
            int r = t >> 2, c = t & 3;
            cp16(&sA[0][r * LDA + c * 8], Ag + (row0 + r) * KKA + c * 8);
        }
        int r = tid >> 3, c = tid & 7;
        cp16(&sB[0][r * LDB + c * 8], Bg + r * NPAD + col0 + c * 8);
        CP_COMMIT();
    }
    int cur = 0;
    for (int kt = 0; kt < 9; ++kt) {
        if (kt < 8) {
            int k0 = (kt + 1) * 32;
            int nxt = cur ^ 1;
#pragma unroll
            for (int t = tid; t < 512; t += 256) {
                int r = t >> 2, c = t & 3;
                cp16(&sA[nxt][r * LDA + c * 8], Ag + (row0 + r) * KKA + k0 + c * 8);
            }
            int r = tid >> 3, c = tid & 7;
            cp16(&sB[nxt][r * LDB + c * 8], Bg + (k0 + r) * NPAD + col0 + c * 8);
            CP_COMMIT();
            CP_WAIT(1);
        } else {
            CP_WAIT(0);
        }
        __syncthreads();
#pragma unroll
        for (int ks = 0; ks < 2; ++ks) {
            wmma::fragment<wmma::matrix_a, 16, 16, 16, __half, wmma::row_major> a0, a1;
            wmma::fragment<wmma::matrix_b, 16, 16, 16, __half, wmma::row_major> b0, b1;
            wmma::load_matrix_sync(a0, &sA[cur][(wm * 32) * LDA + ks * 16], LDA);
            wmma::load_matrix_sync(a1, &sA[cur][(wm * 32 + 16) * LDA + ks * 16], LDA);
            wmma::load_matrix_sync(b0, &sB[cur][(ks * 16) * LDB + wn * 32], LDB);
            wmma::load_matrix_sync(b1, &sB[cur][(ks * 16) * LDB + wn * 32 + 16], LDB);
            wmma::mma_sync(acc[0][0], a0, b0, acc[0][0]);
            wmma::mma_sync(acc[0][1], a0, b1, acc[0][1]);
            wmma::mma_sync(acc[1][0], a1, b0, acc[1][0]);
            wmma::mma_sync(acc[1][1], a1, b1, acc[1][1]);
        }
        __syncthreads();
        cur ^= 1;
    }
    // blocked fp16 epilogue: tile -> per-warp smem -> fp16 global
#pragma unroll
    for (int i = 0; i < 2; ++i)
#pragma unroll
        for (int j = 0; j < 2; ++j) {
            int rt = row0 + wm * 32 + i * 16;     // = k*16
            int ct = col0 + wn * 32 + j * 16;     // = blk16*16
            int k = rt >> 4;
            int blb = ct >> 4;
            wmma::store_matrix_sync(&cbuf[wid][0], acc[i][j], 16, wmma::mem_row_major);
            __syncwarp();
            const float* src = &cbuf[wid][lane * 8];
            __half hb[8];
#pragma unroll
            for (int e = 0; e < 8; ++e) hb[e] = __float2half(src[e]);
            *(uint4*)&g_U2h[k][blb][lane * 8] = *(const uint4*)hb;
            __syncwarp();
        }
}

// ---------------- kernel 4: votes + pass-0 stats, 2 bl per block, fp16 U2 ------
// grid (98, 18). thread map: tid = kh*256 + bb*16 + p (o0 = tid&255, coalesced W).
__global__ void __launch_bounds__(512) k_votes(const float* __restrict__ W,
                                               const float* __restrict__ mb) {
    const int bl0 = blockIdx.x * 2;
    const int k0 = blockIdx.y * 16;
    const int tid = threadIdx.x;      // 512
    __shared__ __align__(16) float Usf[16][16][20];   // [k][pf][pp] pad 20
    __shared__ float sau[16];

    const int kh = tid >> 8;          // 0..1 (k-half)
    const int rr = tid & 255;
    const int bb = rr >> 4;           // 0..15
    const int p  = rr & 15;
    const int o0 = bb * 16 + p;             // = rr (coalesced)
    const int o1 = (bb + 16) * 16 + p;

    float w0[16], w1[16];
    {
        const float4* wv0 = (const float4*)(W + o0 * 16);
        const float4* wv1 = (const float4*)(W + o1 * 16);
#pragma unroll
        for (int f = 0; f < 4; ++f) {
            float4 a = wv0[f], c = wv1[f];
            w0[f * 4 + 0] = a.x; w0[f * 4 + 1] = a.y; w0[f * 4 + 2] = a.z; w0[f * 4 + 3] = a.w;
            w1[f * 4 + 0] = c.x; w1[f * 4 + 1] = c.y; w1[f * 4 + 2] = c.z; w1[f * 4 + 3] = c.w;
        }
    }
    const float gs = 1.f + g_S[p];
    const float sb0 = mb[o0] * gs;
    const float sb1 = mb[o1] * gs;

    // staging indices: each thread converts 8 halves (16B) of one (k,pf) row
    const int sf2 = tid & 1;          // 0..1 (8-half group)
    const int spf = (tid >> 1) & 15;
    const int sk  = tid >> 5;         // 0..15

#pragma unroll 1
    for (int half = 0; half < 2; ++half) {
        const int bl = bl0 + half;
        const int col = bl * PS;
        if (half) __syncthreads();          // protect Usf reuse
        if (tid < 16) sau[tid] = g_au[bl][k0 + tid];
        // stage: y = U2h (fp16, read-once) + PU (fp32)
        {
            const uint4 u = __ldcs((const uint4*)&g_U2h[k0 + sk][bl][spf * 16 + sf2 * 8]);
            const __half2* h = (const __half2*)&u;
            const float4* pr = (const float4*)&g_PU[k0 + sk][col + sf2 * 8];
            float4 r0 = pr[0], r1 = pr[1];
            float2 t0 = __half22float2(h[0]);
            float2 t1 = __half22float2(h[1]);
            float2 t2 = __half22float2(h[2]);
            float2 t3 = __half22float2(h[3]);
            float4 y0, y1;
            y0.x = t0.x + r0.x; y0.y = t0.y + r0.y; y0.z = t1.x + r0.z; y0.w = t1.y + r0.w;
            y1.x = t2.x + r1.x; y1.y = t2.y + r1.y; y1.z = t3.x + r1.z; y1.w = t3.y + r1.w;
            *(float4*)&Usf[sk][spf][sf2 * 8]     = y0;
            *(float4*)&Usf[sk][spf][sf2 * 8 + 4] = y1;
        }
        __syncthreads();
        float aV0 = 0.f, aQ0 = 0.f, aV1 = 0.f, aQ1 = 0.f;
#pragma unroll
        for (int kk = 0; kk < 8; ++kk) {
            int k = kh * 8 + kk;
            const float4* yr = (const float4*)&Usf[k][p][0];
            float4 y0 = yr[0], y1 = yr[1], y2 = yr[2], y3 = yr[3];
            float s0 = sb0, s1 = sb1;
            s0 += y0.x * w0[0]  + y0.y * w0[1]  + y0.z * w0[2]  + y0.w * w0[3];
            s1 += y0.x * w1[0]  + y0.y * w1[1]  + y0.z * w1[2]  + y0.w * w1[3];
            s0 += y1.x * w0[4]  + y1.y * w0[5]  + y1.z * w0[6]  + y1.w * w0[7];
            s1 += y1.x * w1[4]  + y1.y * w1[5]  + y1.z * w1[6]  + y1.w * w1[7];
            s0 += y2.x * w0[8]  + y2.y * w0[9]  + y2.z * w0[10] + y2.w * w0[11];
            s1 += y2.x * w1[8]  + y2.y * w1[9]  + y2.z * w1[10] + y2.w * w1[11];
            s0 += y3.x * w0[12] + y3.y * w0[13] + y3.z * w0[14] + y3.w * w0[15];
            s1 += y3.x * w1[12] + y3.y * w1[13] + y3.z * w1[14] + y3.w * w1[15];
            g_v[bl][k0 + k][bb][p] = s0;
            g_v[bl][k0 + k][bb + 16][p] = s1;
            float auk = sau[k];
            aV0 += auk * s0; aQ0 += auk * s0 * s0;
            aV1 += auk * s1; aQ1 += auk * s1 * s1;
        }
        atomicAdd(&g_pass0[bl][0][o0], aV0);
        atomicAdd(&g_pass0[bl][1][o0], aQ0);
        atomicAdd(&g_pass0[bl][0][o1], aV1);
        atomicAdd(&g_pass0[bl][1][o1], aQ1);
    }
}

// ---------------- kernel 5: fused EM routing (R16 version, unchanged) ----------
__global__ void __launch_bounds__(512) k_em(const float* __restrict__ beta_u,
                                            const float* __restrict__ beta_a,
                                            float* __restrict__ out) {
    const int bl = blockIdx.x;        // 196
    const int tid = threadIdx.x;      // 512
    const int warp = tid >> 5, lane = tid & 31;
    __shared__ float au[KKA];
    __shared__ float accv[32][17], acc2[32][17];
    __shared__ float accr[32];
    __shared__ float mu[32][17], i2s[32][17], sigs[32][17];
    __shared__ float lsum2[32], loga[32], aouts[32], rsum_sh[32];
    __shared__ float wred[16];
    __shared__ float sau_sh;

    for (int i = tid; i < KKA; i += 512) au[i] = g_au[bl][i];
    __syncthreads();
    {
        float s = (tid < KKA) ? au[tid] : 0.f;
#pragma unroll
        for (int o = 16; o; o >>= 1) s += __shfl_xor_sync(~0u, s, o);
        if (lane == 0) wred[warp] = s;
        __syncthreads();
        if (tid == 0) { float t = 0.f; for (int i = 0; i < 16; ++i) t += wred[i]; sau_sh = t; }
        __syncthreads();
    }
    const float* __restrict__ vb = &g_v[bl][0][0][0];
    const int b = tid >> 4, q = tid & 15;
    const float LOG_LN2PI = logf(LN2PI);

    // ---- finalize iter 0 from votes-kernel stats (uniform r) ----
    {
        float rs = sau_sh * (1.f / 32.f);
        float iv = 1.f / (rs + EPSV);
        float m  = g_pass0[bl][0][tid] * (1.f / 32.f) * iv;
        float sg = g_pass0[bl][1][tid] * (1.f / 32.f) * iv - m * m + EPSV;
        mu[b][q] = m; sigs[b][q] = sg; i2s[b][q] = 0.5f / sg;
        if (tid < 32) rsum_sh[tid] = rs;
    }
    __syncthreads();
    if (tid < 32) {
        float ls = 0.f;
#pragma unroll
        for (int j = 0; j < 16; ++j) ls += logf(sigs[tid][j]);
        float cost = rsum_sh[tid] * (16.f * beta_u[tid] + 0.5f * ls);
        float z = 5.0e-4f * (beta_a[tid] - cost);
        float ao = 1.f / (1.f + expf(-z));
        aouts[tid] = ao; loga[tid] = logf(ao);
        lsum2[tid] = ls + 16.f * LOG_LN2PI;
    }
    __syncthreads();

    // ---- fused passes: e-step(it) + stats(it+1), prefetched v stream ----
#pragma unroll 1
    for (int it = 0; it < 2; ++it) {
        for (int i = tid; i < 32 * 17; i += 512) { (&accv[0][0])[i] = 0.f; (&acc2[0][0])[i] = 0.f; }
        if (tid < 32) accr[tid] = 0.f;
        __syncthreads();
        float A[16], TMA[16];
        float Kc;
        {
            float cst = 0.f;
#pragma unroll
            for (int j = 0; j < 16; ++j) {
                float m = mu[lane][j], ai = i2s[lane][j];
                A[j] = ai; TMA[j] = 2.f * m * ai;
                cst += m * m * ai;
            }
            Kc = loga[lane] - 0.5f * lsum2[lane] - cst;
        }
        float av[16], a2[16], ar = 0.f;
#pragma unroll
        for (int j = 0; j < 16; ++j) { av[j] = 0.f; a2[j] = 0.f; }

        // prologue prefetch (k = warp)
        float4 n0, n1, n2, n3;
        {
            const float4* vp = (const float4*)(vb + (warp * 32 + lane) * 16);
            n0 = vp[0]; n1 = vp[1]; n2 = vp[2]; n3 = vp[3];
        }
#pragma unroll 1
        for (int k = warp; k < KKA; k += 16) {
            float4 q0 = n0, q1 = n1, q2 = n2, q3 = n3;
            int kn = k + 16;
            if (kn < KKA) {
                const float4* vp = (const float4*)(vb + (kn * 32 + lane) * 16);
                n0 = vp[0]; n1 = vp[1]; n2 = vp[2]; n3 = vp[3];
            }
            // 4 independent partial chains (tree), then combine
            float s0, s1, s2, s3;
            s0  = q0.x * fmaf(-A[0],  q0.x, TMA[0]);
            s0  = fmaf(q0.y, fmaf(-A[1],  q0.y, TMA[1]),  s0);
            s0  = fmaf(q0.z, fmaf(-A[2],  q0.z, TMA[2]),  s0);
            s0  = fmaf(q0.w, fmaf(-A[3],  q0.w, TMA[3]),  s0);
            s1  = q1.x * fmaf(-A[4],  q1.x, TMA[4]);
            s1  = fmaf(q1.y, fmaf(-A[5],  q1.y, TMA[5]),  s1);
            s1  = fmaf(q1.z, fmaf(-A[6],  q1.z, TMA[6]),  s1);
            s1  = fmaf(q1.w, fmaf(-A[7],  q1.w, TMA[7]),  s1);
            s2  = q2.x * fmaf(-A[8],  q2.x, TMA[8]);
            s2  = fmaf(q2.y, fmaf(-A[9],  q2.y, TMA[9]),  s2);
            s2  = fmaf(q2.z, fmaf(-A[10], q2.z, TMA[10]), s2);
            s2  = fmaf(q2.w, fmaf(-A[11], q2.w, TMA[11]), s2);
            s3  = q3.x * fmaf(-A[12], q3.x, TMA[12]);
            s3  = fmaf(q3.y, fmaf(-A[13], q3.y, TMA[13]), s3);
            s3  = fmaf(q3.z, fmaf(-A[14], q3.z, TMA[14]), s3);
            s3  = fmaf(q3.w, fmaf(-A[15], q3.w, TMA[15]), s3);
            float lnap = Kc + ((s0 + s1) + (s2 + s3));
            float mx = warp_redux_max_f32(lnap);
            float e = __expf(lnap - mx);
            float se = e;
#pragma unroll
            for (int o = 16; o; o >>= 1) se += __shfl_xor_sync(~0u, se, o);
            float c = __fdividef(e, se) * au[k];
            ar += c;
            float t;
            t = c * q0.x; av[0]  += t; a2[0]  = fmaf(t, q0.x, a2[0]);
            t = c * q0.y; av[1]  += t; a2[1]  = fmaf(t, q0.y, a2[1]);
            t = c * q0.z; av[2]  += t; a2[2]  = fmaf(t, q0.z, a2[2]);
            t = c * q0.w; av[3]  += t; a2[3]  = fmaf(t, q0.w, a2[3]);
            t = c * q1.x; av[4]  += t; a2[4]  = fmaf(t, q1.x, a2[4]);
            t = c * q1.y; av[5]  += t; a2[5]  = fmaf(t, q1.y, a2[5]);
            t = c * q1.z; av[6]  += t; a2[6]  = fmaf(t, q1.z, a2[6]);
            t = c * q1.w; av[7]  += t; a2[7]  = fmaf(t, q1.w, a2[7]);
            t = c * q2.x; av[8]  += t; a2[8]  = fmaf(t, q2.x, a2[8]);
            t = c * q2.y; av[9]  += t; a2[9]  = fmaf(t, q2.y, a2[9]);
            t = c * q2.z; av[10] += t; a2[10] = fmaf(t, q2.z, a2[10]);
            t = c * q2.w; av[11] += t; a2[11] = fmaf(t, q2.w, a2[11]);
            t = c * q3.x; av[12] += t; a2[12] = fmaf(t, q3.x, a2[12]);
            t = c * q3.y; av[13] += t; a2[13] = fmaf(t, q3.y, a2[13]);
            t = c * q3.z; av[14] += t; a2[14] = fmaf(t, q3.z, a2[14]);
            t = c * q3.w; av[15] += t; a2[15] = fmaf(t, q3.w, a2[15]);
        }
#pragma unroll
        for (int j = 0; j < 16; ++j) {
            atomicAdd(&accv[lane][j], av[j]);
            atomicAdd(&acc2[lane][j], a2[j]);
        }
        atomicAdd(&accr[lane], ar);
        __syncthreads();
        {
            float rs = accr[b];
            float iv = 1.f / (rs + EPSV);
            float m  = accv[b][q] * iv;
            float sg = acc2[b][q] * iv - m * m + EPSV;
            mu[b][q] = m; sigs[b][q] = sg; i2s[b][q] = 0.5f / sg;
            if (tid < 32) rsum_sh[tid] = accr[tid];
        }
        __syncthreads();
        if (tid < 32) {
            float ls = 0.f;
#pragma unroll
            for (int j = 0; j < 16; ++j) ls += logf(sigs[tid][j]);
            float cost = rsum_sh[tid] * (16.f * beta_u[tid] + 0.5f * ls);
            float lam = (it == 0) ? 9.75e-4f : 1.42625e-3f;
            float z = lam * (beta_a[tid] - cost);
            float ao = 1.f / (1.f + expf(-z));
            aouts[tid] = ao; loga[tid] = logf(ao);
            lsum2[tid] = ls + 16.f * LOG_LN2PI;
        }
        __syncthreads();
    }
    // outputs: a_fin [BATCH][32][7][7] then pose_out [BATCH][512][7][7]
    int batch = bl / L, pos = bl - batch * L;
    if (tid < 32) out[(batch * 32 + tid) * L + pos] = aouts[tid];
    out[BATCH * 32 * L + (batch * 512 + tid) * L + pos] = mu[b][q];
}

// ---------------- launch ----------------
extern "C" void kernel_launch(void* const* d_in, const int* in_sizes, int n_in,
                              void* d_out, int out_size) {
    const float* a_in   = (const float*)d_in[0];
    const float* pose   = (const float*)d_in[1];
    const float* mposew = (const float*)d_in[2];
    const float* mposeb = (const float*)d_in[3];
    const float* freqw  = (const float*)d_in[4];
    const float* beta_u = (const float*)d_in[9];
    const float* beta_a = (const float*)d_in[10];
    float* out = (float*)d_out;

    k_build_h<<<16, KKA>>>(freqw);
    k_setup<<<128 + (16 * KKA * KKA + 255) / 256, 256>>>(pose, a_in);
    k_gemm<<<dim3(NPAD / 64, GM / 128), 256>>>();
    k_votes<<<dim3(BL / 2, 18), 512>>>(mposew, mposeb);
    k_em<<<BL, 512>>>(beta_u, beta_a, out);
}